// round 1
// baseline (speedup 1.0000x reference)
#include <cuda_runtime.h>
#include <math.h>

#define B_   8192
#define F_   32
#define V_   64
#define C_   32
#define K_   8
#define KP_  7
#define FM1  31
#define EPS_ 1e-6f

// Scratch (no cudaMalloc allowed)
__device__ float g_w[FM1 * K_];                        // gate weights (31,8)
__device__ float g_T[F_ * V_ * C_];                    // fused gather table (32,64,32) = 256KB
__device__ float g_lsep[FM1 * KP_ * V_ * C_];          // pair LSE (f,k,v2,c) = 1.74MB

// ---------------------------------------------------------------------------
// Kernel 0: gumbel-softmax gate weights w (31 rows of 8, masked softmax)
// ---------------------------------------------------------------------------
__global__ void k_gates(const float* __restrict__ sl, const float* __restrict__ un) {
    int i = threadIdx.x;
    if (i >= FM1) return;
    int nv = 1 + ((i + 1 < KP_) ? (i + 1) : KP_);   // valid gates: k=0 plus k=1..min(i+1,7)
    float gate[K_];
    float m = -1e30f;
    for (int k = 0; k < K_; k++) {
        if (k < nv) {
            float u = un[i * K_ + k];
            float g = -logf(-logf(u + EPS_) + EPS_);
            gate[k] = sl[i * K_ + k] + g;
            m = fmaxf(m, gate[k]);
        }
    }
    float s = 0.f;
    for (int k = 0; k < K_; k++) {
        if (k < nv) { gate[k] = expf(gate[k] - m); s += gate[k]; }
    }
    float inv = 1.f / s;
    for (int k = 0; k < K_; k++)
        g_w[i * K_ + k] = (k < nv) ? gate[k] * inv : 0.f;
}

// ---------------------------------------------------------------------------
// Kernel 1: build T from class_logits + table0 (block 0) and self_tables
// (blocks 1..31).  T[j,v,c] indexed by x-column j.
// ---------------------------------------------------------------------------
__global__ void k_build_T(const float* __restrict__ cls,
                          const float* __restrict__ t0,
                          const float* __restrict__ st) {
    __shared__ float s_lse[C_];
    __shared__ float s_cl;
    int j   = blockIdx.x;
    int tid = threadIdx.x;

    if (j == 0) {
        if (tid == 0) {
            float m = -1e30f;
            for (int c = 0; c < C_; c++) m = fmaxf(m, cls[c]);
            float s = 0.f;
            for (int c = 0; c < C_; c++) s += expf(cls[c] - m);
            s_cl = m + logf(s);
        }
        if (tid < C_) {
            float m = -1e30f;
            for (int v = 0; v < V_; v++) m = fmaxf(m, t0[v * C_ + tid]);
            float s = 0.f;
            for (int v = 0; v < V_; v++) s += expf(t0[v * C_ + tid] - m);
            s_lse[tid] = m + logf(s);
        }
        __syncthreads();
        for (int p = tid; p < V_ * C_; p += blockDim.x) {
            int c = p & (C_ - 1);
            g_T[p] = (cls[c] - s_cl) + (t0[p] - s_lse[c]);
        }
    } else {
        int f = j - 1;
        const float* stf = st + f * V_ * C_;
        if (tid < C_) {
            float m = -1e30f;
            for (int v = 0; v < V_; v++) m = fmaxf(m, stf[v * C_ + tid]);
            float s = 0.f;
            for (int v = 0; v < V_; v++) s += expf(stf[v * C_ + tid] - m);
            s_lse[tid] = m + logf(s);
        }
        __syncthreads();
        float w0 = g_w[f * K_ + 0];
        for (int p = tid; p < V_ * C_; p += blockDim.x) {
            int c = p & (C_ - 1);
            g_T[j * V_ * C_ + p] = w0 * (stf[p] - s_lse[c]);
        }
    }
}

// ---------------------------------------------------------------------------
// Kernel 2: pair-table LSE over the v axis (axis 2).
// One block per (f,k); 1024 threads; float2 per thread covers a full 2048-float
// (v2,c) slab. Streams 113.8MB once; direct sum-exp is safe (|x| small, fp32).
// ---------------------------------------------------------------------------
__global__ void __launch_bounds__(1024) k_pair_lse(const float* __restrict__ pt) {
    int fk = blockIdx.x;
    const float* base = pt + (size_t)fk * (V_ * V_ * C_);
    int t = threadIdx.x;
    float s0 = 0.f, s1 = 0.f;
#pragma unroll 8
    for (int v = 0; v < V_; v++) {
        const float2 row = __ldg(((const float2*)(base + v * (V_ * C_))) + t);
        s0 += __expf(row.x);
        s1 += __expf(row.y);
    }
    float2 r;
    r.x = __logf(s0);
    r.y = __logf(s1);
    ((float2*)(g_lsep + fk * 2048))[t] = r;
}

// ---------------------------------------------------------------------------
// Kernel 3: fold the weighted pair-LSE corrections into T.
// x-column m receives  -sum_j w[m+j, j+1] * lse_pair[m+j, j, v, c].
// ---------------------------------------------------------------------------
__global__ void k_fold_M() {
    int m    = blockIdx.x;            // 0..30
    int jmax = (6 < 30 - m) ? 6 : (30 - m);
    for (int p = threadIdx.x; p < V_ * C_; p += blockDim.x) {
        float acc = 0.f;
        for (int jj = 0; jj <= jmax; jj++) {
            int i = m + jj;
            acc += g_w[i * K_ + jj + 1] * g_lsep[(i * KP_ + jj) * (V_ * C_) + p];
        }
        g_T[m * V_ * C_ + p] -= acc;
    }
}

// ---------------------------------------------------------------------------
// Kernel 4: main gather-accumulate. One warp per batch element, lane = class c.
// ---------------------------------------------------------------------------
__global__ void __launch_bounds__(256) k_main(const int* __restrict__ x,
                                              const float* __restrict__ pt,
                                              float* __restrict__ out) {
    __shared__ float s_w[FM1 * K_];
    for (int p = threadIdx.x; p < FM1 * K_; p += blockDim.x) s_w[p] = g_w[p];
    __syncthreads();

    int warp = threadIdx.x >> 5;
    int lane = threadIdx.x & 31;
    int b    = blockIdx.x * 8 + warp;

    // Load the full x row into registers (uniform address per warp -> L1 broadcast)
    const int4* xr = (const int4*)(x + b * F_);
    int xv[F_];
#pragma unroll
    for (int q = 0; q < 8; q++) {
        int4 v = __ldg(&xr[q]);
        xv[4 * q + 0] = v.x; xv[4 * q + 1] = v.y;
        xv[4 * q + 2] = v.z; xv[4 * q + 3] = v.w;
    }

    float a0 = 0.f, a1 = 0.f, a2 = 0.f, a3 = 0.f;

    // Fused-table gathers (base + self + LSE corrections): 32 x 128B
#pragma unroll
    for (int j = 0; j < F_; j++) {
        float t = __ldg(&g_T[(j * V_ + xv[j]) * C_ + lane]);
        if (j & 1) a1 += t; else a0 += t;
    }

    // Pair-table gathers: <=196 x 128B, weight FMA with smem-broadcast w
#pragma unroll
    for (int i = 0; i < FM1; i++) {
        int vsOff = xv[i + 1] * (V_ * C_);
        const int nk = (i + 1 < KP_) ? (i + 1) : KP_;
#pragma unroll
        for (int k = 0; k < nk; k++) {
            int off   = (i * KP_ + k) * (V_ * V_ * C_) + vsOff + xv[i - k] * C_ + lane;
            float val = __ldg(&pt[off]);
            float w   = s_w[i * K_ + k + 1];
            if (k & 1) a3 = fmaf(w, val, a3); else a2 = fmaf(w, val, a2);
        }
    }

    out[b * C_ + lane] = (a0 + a1) + (a2 + a3);
}

// ---------------------------------------------------------------------------
extern "C" void kernel_launch(void* const* d_in, const int* in_sizes, int n_in,
                              void* d_out, int out_size) {
    // Input order: x, [training], class_logits, table0, self_tables,
    //              pair_tables, structure_logits, u_noise, cond_index, valid_mask
    const int* x = (const int*)d_in[0];
    int idx = 1;
    if (in_sizes[1] == 1) idx = 2;   // skip scalar 'training' if present
    const float* cls = (const float*)d_in[idx++];
    const float* t0  = (const float*)d_in[idx++];
    const float* st  = (const float*)d_in[idx++];
    const float* pt  = (const float*)d_in[idx++];
    const float* sl  = (const float*)d_in[idx++];
    const float* un  = (const float*)d_in[idx++];
    float* out = (float*)d_out;

    k_gates<<<1, 32>>>(sl, un);
    k_build_T<<<32, 256>>>(cls, t0, st);
    k_pair_lse<<<FM1 * KP_, 1024>>>(pt);
    k_fold_M<<<FM1, 256>>>();
    k_main<<<B_ / 8, 256>>>(x, pt, out);
}

// round 2
// speedup vs baseline: 1.1726x; 1.1726x over previous
#include <cuda_runtime.h>
#include <math.h>

#define B_   8192
#define F_   32
#define V_   64
#define C_   32
#define K_   8
#define KP_  7
#define FM1  31
#define EPS_ 1e-6f
#define VC_  (V_ * C_)          // 2048
#define VVC_ (V_ * V_ * C_)     // 131072

// Scratch (no cudaMalloc allowed)
__device__ float g_T[F_ * VC_];              // fused gather table (32,64,32) = 256KB
__device__ float g_lsep[FM1 * KP_ * VC_];    // pair LSE (f,k,v2,c) = 1.74MB

// ---------------------------------------------------------------------------
// Gate-row helper: gumbel-softmax weights for structure row i (0..30).
// ~60 flops; recomputed in-block wherever needed (cheaper than a launch).
// ---------------------------------------------------------------------------
__device__ __forceinline__ void gate_row(int i, const float* __restrict__ sl,
                                         const float* __restrict__ un,
                                         float* __restrict__ wout) {
    int nv = 1 + ((i + 1 < KP_) ? (i + 1) : KP_);
    float gate[K_];
    float m = -1e30f;
#pragma unroll
    for (int k = 0; k < K_; k++) {
        if (k < nv) {
            float u = un[i * K_ + k];
            float g = -logf(-logf(u + EPS_) + EPS_);
            gate[k] = sl[i * K_ + k] + g;
            m = fmaxf(m, gate[k]);
        }
    }
    float s = 0.f;
#pragma unroll
    for (int k = 0; k < K_; k++)
        if (k < nv) { gate[k] = expf(gate[k] - m); s += gate[k]; }
    float inv = 1.f / s;
#pragma unroll
    for (int k = 0; k < K_; k++)
        wout[k] = (k < nv) ? gate[k] * inv : 0.f;
}

// ---------------------------------------------------------------------------
// Kernel 1 (fused prep): blocks 0..31 build T rows; blocks 32..899 compute
// pair-table LSE over axis v1 (4 blocks per (f,k) slab for load balance).
// ---------------------------------------------------------------------------
__global__ void __launch_bounds__(256) k_prep(const float* __restrict__ cls,
                                              const float* __restrict__ t0,
                                              const float* __restrict__ st,
                                              const float* __restrict__ pt,
                                              const float* __restrict__ sl,
                                              const float* __restrict__ un) {
    int bid = blockIdx.x;
    int tid = threadIdx.x;

    if (bid >= 32) {
        // ---- pair LSE: slab = (f,k), quarter of the (v2,c) plane ----
        int q    = bid - 32;
        int fk   = q >> 2;               // 0..216
        int part = q & 3;
        const float2* base = (const float2*)(pt + (size_t)fk * VVC_);
        int t = part * 256 + tid;        // float2 index within 1024-wide plane
        float s0 = 0.f, s1 = 0.f;
#pragma unroll 8
        for (int v = 0; v < V_; v++) {
            float2 row = __ldg(base + v * (VC_ / 2) + t);
            s0 += __expf(row.x);
            s1 += __expf(row.y);
        }
        float2 r; r.x = __logf(s0); r.y = __logf(s1);
        ((float2*)(g_lsep + fk * VC_))[t] = r;
        return;
    }

    // ---- build T row j ----
    __shared__ float s_lse[C_];
    __shared__ float s_scalar;           // cl-lse (j==0) or w0 (j>0)
    int j = bid;

    if (j == 0) {
        if (tid == 0) {
            float m = -1e30f;
            for (int c = 0; c < C_; c++) m = fmaxf(m, cls[c]);
            float s = 0.f;
            for (int c = 0; c < C_; c++) s += expf(cls[c] - m);
            s_scalar = m + logf(s);
        }
        if (tid < C_) {
            float m = -1e30f;
            for (int v = 0; v < V_; v++) m = fmaxf(m, t0[v * C_ + tid]);
            float s = 0.f;
            for (int v = 0; v < V_; v++) s += expf(t0[v * C_ + tid] - m);
            s_lse[tid] = m + logf(s);
        }
        __syncthreads();
        for (int p = tid; p < VC_; p += blockDim.x) {
            int c = p & (C_ - 1);
            g_T[p] = (cls[c] - s_scalar) + (t0[p] - s_lse[c]);
        }
    } else {
        int f = j - 1;
        const float* stf = st + f * VC_;
        if (tid == 0) {
            float w[K_];
            gate_row(f, sl, un, w);
            s_scalar = w[0];
        }
        if (tid < C_) {
            float m = -1e30f;
            for (int v = 0; v < V_; v++) m = fmaxf(m, stf[v * C_ + tid]);
            float s = 0.f;
            for (int v = 0; v < V_; v++) s += expf(stf[v * C_ + tid] - m);
            s_lse[tid] = m + logf(s);
        }
        __syncthreads();
        float w0 = s_scalar;
        for (int p = tid; p < VC_; p += blockDim.x) {
            int c = p & (C_ - 1);
            g_T[j * VC_ + p] = w0 * (stf[p] - s_lse[c]);
        }
    }
}

// ---------------------------------------------------------------------------
// Kernel 2: fold weighted pair-LSE corrections into T.
// One thread per output element (31*2048 = 63488 = 62 blocks x 1024 threads).
// x-column m receives  -sum_jj w[m+jj, jj+1] * lse_pair[m+jj, jj, v, c].
// ---------------------------------------------------------------------------
__global__ void __launch_bounds__(1024) k_fold(const float* __restrict__ sl,
                                               const float* __restrict__ un) {
    __shared__ float s_w[FM1 * K_];
    if (threadIdx.x < FM1) gate_row(threadIdx.x, sl, un, &s_w[threadIdx.x * K_]);
    __syncthreads();

    int e = blockIdx.x * 1024 + threadIdx.x;
    int m = e >> 11;                     // 0..30
    int p = e & (VC_ - 1);
    int jmax = (6 < 30 - m) ? 6 : (30 - m);
    float acc = 0.f;
#pragma unroll
    for (int jj = 0; jj < KP_; jj++) {
        if (jj <= jmax) {
            int i = m + jj;
            acc = fmaf(s_w[i * K_ + jj + 1],
                       __ldg(&g_lsep[(i * KP_ + jj) * VC_ + p]), acc);
        }
    }
    g_T[m * VC_ + p] -= acc;
}

// ---------------------------------------------------------------------------
// Kernel 3: main gather-accumulate. One warp per batch element, lane = class.
// ---------------------------------------------------------------------------
__global__ void __launch_bounds__(256) k_main(const int* __restrict__ x,
                                              const float* __restrict__ pt,
                                              const float* __restrict__ sl,
                                              const float* __restrict__ un,
                                              float* __restrict__ out) {
    __shared__ float s_w[FM1 * K_];
    if (threadIdx.x < FM1) gate_row(threadIdx.x, sl, un, &s_w[threadIdx.x * K_]);
    __syncthreads();

    int warp = threadIdx.x >> 5;
    int lane = threadIdx.x & 31;
    int b    = blockIdx.x * 8 + warp;

    const int4* xr = (const int4*)(x + b * F_);
    int xv[F_];
#pragma unroll
    for (int q = 0; q < 8; q++) {
        int4 v = __ldg(&xr[q]);
        xv[4 * q + 0] = v.x; xv[4 * q + 1] = v.y;
        xv[4 * q + 2] = v.z; xv[4 * q + 3] = v.w;
    }

    float a0 = 0.f, a1 = 0.f, a2 = 0.f, a3 = 0.f;

    // Fused-table gathers (base + self + all LSE corrections): 32 x 128B
#pragma unroll
    for (int j = 0; j < F_; j++) {
        float t = __ldg(&g_T[(j * V_ + xv[j]) * C_ + lane]);
        if (j & 1) a1 += t; else a0 += t;
    }

    // Raw pair-table gathers: <=196 x 128B lines, weighted by smem gates
#pragma unroll
    for (int i = 0; i < FM1; i++) {
        int vsOff = xv[i + 1] * VC_;
        const int nk = (i + 1 < KP_) ? (i + 1) : KP_;
#pragma unroll
        for (int k = 0; k < nk; k++) {
            int off   = (i * KP_ + k) * VVC_ + vsOff + xv[i - k] * C_ + lane;
            float val = __ldg(&pt[off]);
            float w   = s_w[i * K_ + k + 1];
            if (k & 1) a3 = fmaf(w, val, a3); else a2 = fmaf(w, val, a2);
        }
    }

    out[b * C_ + lane] = (a0 + a1) + (a2 + a3);
}

// ---------------------------------------------------------------------------
extern "C" void kernel_launch(void* const* d_in, const int* in_sizes, int n_in,
                              void* d_out, int out_size) {
    // Input order: x, [training], class_logits, table0, self_tables,
    //              pair_tables, structure_logits, u_noise, cond_index, valid_mask
    const int* x = (const int*)d_in[0];
    int idx = 1;
    if (in_sizes[1] == 1) idx = 2;   // skip scalar 'training' if present
    const float* cls = (const float*)d_in[idx++];
    const float* t0  = (const float*)d_in[idx++];
    const float* st  = (const float*)d_in[idx++];
    const float* pt  = (const float*)d_in[idx++];
    const float* sl  = (const float*)d_in[idx++];
    const float* un  = (const float*)d_in[idx++];
    float* out = (float*)d_out;

    k_prep<<<32 + FM1 * KP_ * 4, 256>>>(cls, t0, st, pt, sl, un);
    k_fold<<<62, 1024>>>(sl, un);
    k_main<<<B_ / 8, 256>>>(x, pt, sl, un, out);
}

// round 3
// speedup vs baseline: 1.2881x; 1.0985x over previous
#include <cuda_runtime.h>
#include <math.h>

#define B_   8192
#define F_   32
#define V_   64
#define C_   32
#define K_   8
#define KP_  7
#define FM1  31
#define EPS_ 1e-6f
#define VC_  (V_ * C_)          // 2048
#define VVC_ (V_ * V_ * C_)     // 131072
#define NFK  (FM1 * KP_)        // 217

// Scratch (no cudaMalloc allowed)
__device__ float g_T[F_ * VC_];              // fused gather table (32,64,32) = 256KB
__device__ float g_sexp[NFK * 2 * VC_];      // pair exp-sum partials (fk, vhalf, v2*c) = 3.55MB

// ---------------------------------------------------------------------------
// Gate-row helper: gumbel-softmax weights for structure row i (0..30).
// ---------------------------------------------------------------------------
__device__ __forceinline__ void gate_row(int i, const float* __restrict__ sl,
                                         const float* __restrict__ un,
                                         float* __restrict__ wout) {
    int nv = 1 + ((i + 1 < KP_) ? (i + 1) : KP_);
    float gate[K_];
    float m = -1e30f;
#pragma unroll
    for (int k = 0; k < K_; k++) {
        if (k < nv) {
            float u = un[i * K_ + k];
            float g = -logf(-logf(u + EPS_) + EPS_);
            gate[k] = sl[i * K_ + k] + g;
            m = fmaxf(m, gate[k]);
        }
    }
    float s = 0.f;
#pragma unroll
    for (int k = 0; k < K_; k++)
        if (k < nv) { gate[k] = expf(gate[k] - m); s += gate[k]; }
    float inv = 1.f / s;
#pragma unroll
    for (int k = 0; k < K_; k++)
        wout[k] = (k < nv) ? gate[k] * inv : 0.f;
}

// ---------------------------------------------------------------------------
// Kernel 1 (fused prep): blocks 0..31 build T rows; blocks 32..899 compute
// pair-table exp-sum partials (float4 loads, half the v-range per block).
// ---------------------------------------------------------------------------
__global__ void __launch_bounds__(256) k_prep(const float* __restrict__ cls,
                                              const float* __restrict__ t0,
                                              const float* __restrict__ st,
                                              const float* __restrict__ pt,
                                              const float* __restrict__ sl,
                                              const float* __restrict__ un) {
    int bid = blockIdx.x;
    int tid = threadIdx.x;

    if (bid >= 32) {
        // ---- pair exp-sums: (fk, part half of plane, half of v-range) ----
        int q     = bid - 32;            // 0..867
        int fk    = q >> 2;              // 0..216
        int part  = q & 1;
        int vhalf = (q >> 1) & 1;
        const float4* base = (const float4*)(pt + (size_t)fk * VVC_)
                             + vhalf * 32 * (VC_ / 4);
        int t = part * 256 + tid;        // float4 index within 512-wide plane
        float s0 = 0.f, s1 = 0.f, s2 = 0.f, s3 = 0.f;
#pragma unroll 8
        for (int v = 0; v < 32; v++) {
            float4 r = __ldg(base + v * (VC_ / 4) + t);
            s0 += __expf(r.x); s1 += __expf(r.y);
            s2 += __expf(r.z); s3 += __expf(r.w);
        }
        float4 o; o.x = s0; o.y = s1; o.z = s2; o.w = s3;
        ((float4*)(g_sexp + (fk * 2 + vhalf) * VC_))[t] = o;
        return;
    }

    // ---- build T row j ----
    __shared__ float s_lse[C_];
    __shared__ float s_scalar;           // cl-lse (j==0) or w0 (j>0)
    int j = bid;

    if (j == 0) {
        if (tid == 0) {
            float m = -1e30f;
            for (int c = 0; c < C_; c++) m = fmaxf(m, cls[c]);
            float s = 0.f;
            for (int c = 0; c < C_; c++) s += expf(cls[c] - m);
            s_scalar = m + logf(s);
        }
        if (tid < C_) {
            float m = -1e30f;
            for (int v = 0; v < V_; v++) m = fmaxf(m, t0[v * C_ + tid]);
            float s = 0.f;
            for (int v = 0; v < V_; v++) s += expf(t0[v * C_ + tid] - m);
            s_lse[tid] = m + logf(s);
        }
        __syncthreads();
        for (int p = tid; p < VC_; p += blockDim.x) {
            int c = p & (C_ - 1);
            g_T[p] = (cls[c] - s_scalar) + (t0[p] - s_lse[c]);
        }
    } else {
        int f = j - 1;
        const float* stf = st + f * VC_;
        if (tid == 0) {
            float w[K_];
            gate_row(f, sl, un, w);
            s_scalar = w[0];
        }
        if (tid < C_) {
            float m = -1e30f;
            for (int v = 0; v < V_; v++) m = fmaxf(m, stf[v * C_ + tid]);
            float s = 0.f;
            for (int v = 0; v < V_; v++) s += expf(stf[v * C_ + tid] - m);
            s_lse[tid] = m + logf(s);
        }
        __syncthreads();
        float w0 = s_scalar;
        for (int p = tid; p < VC_; p += blockDim.x) {
            int c = p & (C_ - 1);
            g_T[j * VC_ + p] = w0 * (stf[p] - s_lse[c]);
        }
    }
}

// ---------------------------------------------------------------------------
// Kernel 2: fold weighted pair-LSE corrections into T (log done here).
// One thread per element (31*2048 = 63488 = 62 blocks x 1024 threads).
// ---------------------------------------------------------------------------
__global__ void __launch_bounds__(1024) k_fold(const float* __restrict__ sl,
                                               const float* __restrict__ un) {
    __shared__ float s_w[FM1 * K_];
    if (threadIdx.x < FM1) gate_row(threadIdx.x, sl, un, &s_w[threadIdx.x * K_]);
    __syncthreads();

    int e = blockIdx.x * 1024 + threadIdx.x;
    int m = e >> 11;                     // 0..30
    int p = e & (VC_ - 1);
    int jmax = (6 < 30 - m) ? 6 : (30 - m);
    float acc = 0.f;
#pragma unroll
    for (int jj = 0; jj < KP_; jj++) {
        if (jj <= jmax) {
            int i  = m + jj;
            int fk = i * KP_ + jj;
            float s = __ldg(&g_sexp[(fk * 2 + 0) * VC_ + p])
                    + __ldg(&g_sexp[(fk * 2 + 1) * VC_ + p]);
            acc = fmaf(s_w[i * K_ + jj + 1], __logf(s), acc);
        }
    }
    g_T[m * VC_ + p] -= acc;
}

// ---------------------------------------------------------------------------
// Kernel 3: main gather-accumulate. TWO warps per batch element (split the
// feature range), lane = class, smem combine. Halves the per-warp serial
// gather chain and register pressure.
// ---------------------------------------------------------------------------
__global__ void __launch_bounds__(256) k_main(const int* __restrict__ x,
                                              const float* __restrict__ pt,
                                              const float* __restrict__ sl,
                                              const float* __restrict__ un,
                                              float* __restrict__ out) {
    __shared__ float s_w[FM1 * K_];
    __shared__ float s_part[8][C_];
    if (threadIdx.x < FM1) gate_row(threadIdx.x, sl, un, &s_w[threadIdx.x * K_]);
    __syncthreads();

    int warp = threadIdx.x >> 5;
    int lane = threadIdx.x & 31;
    int half = warp & 1;
    int b    = blockIdx.x * 4 + (warp >> 1);

    const int4* xr = (const int4*)(x + b * F_);
    float a0 = 0.f, a1 = 0.f, a2 = 0.f, a3 = 0.f;

    if (half == 0) {
        // x columns 0..15
        int xv[16];
#pragma unroll
        for (int q = 0; q < 4; q++) {
            int4 v = __ldg(&xr[q]);
            xv[4 * q + 0] = v.x; xv[4 * q + 1] = v.y;
            xv[4 * q + 2] = v.z; xv[4 * q + 3] = v.w;
        }
        // T gathers j = 0..15
#pragma unroll
        for (int j = 0; j < 16; j++) {
            float t = __ldg(&g_T[(j * V_ + xv[j]) * C_ + lane]);
            if (j & 1) a1 += t; else a0 += t;
        }
        // pair gathers i = 0..14  (xs = xv[i+1], xc = xv[i-k], all <= 15)
#pragma unroll
        for (int i = 0; i < 15; i++) {
            int vsOff = xv[i + 1] * VC_;
            const int nk = (i + 1 < KP_) ? (i + 1) : KP_;
#pragma unroll
            for (int k = 0; k < nk; k++) {
                int off   = (i * KP_ + k) * VVC_ + vsOff + xv[i - k] * C_ + lane;
                float val = __ldg(&pt[off]);
                float w   = s_w[i * K_ + k + 1];
                if (k & 1) a3 = fmaf(w, val, a3); else a2 = fmaf(w, val, a2);
            }
        }
    } else {
        // x columns 8..31 (pairs i=15..30 need xc down to column 9)
        int xv[24];
#pragma unroll
        for (int q = 2; q < 8; q++) {
            int4 v = __ldg(&xr[q]);
            xv[4 * q - 8] = v.x; xv[4 * q - 7] = v.y;
            xv[4 * q - 6] = v.z; xv[4 * q - 5] = v.w;
        }
        // T gathers j = 16..31
#pragma unroll
        for (int j = 16; j < 32; j++) {
            float t = __ldg(&g_T[(j * V_ + xv[j - 8]) * C_ + lane]);
            if (j & 1) a1 += t; else a0 += t;
        }
        // pair gathers i = 15..30 (nk == 7 for all)
#pragma unroll
        for (int i = 15; i < FM1; i++) {
            int vsOff = xv[i + 1 - 8] * VC_;
#pragma unroll
            for (int k = 0; k < KP_; k++) {
                int off   = (i * KP_ + k) * VVC_ + vsOff + xv[i - k - 8] * C_ + lane;
                float val = __ldg(&pt[off]);
                float w   = s_w[i * K_ + k + 1];
                if (k & 1) a3 = fmaf(w, val, a3); else a2 = fmaf(w, val, a2);
            }
        }
    }

    float r = (a0 + a1) + (a2 + a3);
    s_part[warp][lane] = r;
    __syncthreads();
    if (half == 0)
        out[b * C_ + lane] = r + s_part[warp + 1][lane];
}

// ---------------------------------------------------------------------------
extern "C" void kernel_launch(void* const* d_in, const int* in_sizes, int n_in,
                              void* d_out, int out_size) {
    const int* x = (const int*)d_in[0];
    int idx = 1;
    if (in_sizes[1] == 1) idx = 2;   // skip scalar 'training' if present
    const float* cls = (const float*)d_in[idx++];
    const float* t0  = (const float*)d_in[idx++];
    const float* st  = (const float*)d_in[idx++];
    const float* pt  = (const float*)d_in[idx++];
    const float* sl  = (const float*)d_in[idx++];
    const float* un  = (const float*)d_in[idx++];
    float* out = (float*)d_out;

    k_prep<<<32 + NFK * 4, 256>>>(cls, t0, st, pt, sl, un);
    k_fold<<<62, 1024>>>(sl, un);
    k_main<<<B_ / 4, 256>>>(x, pt, sl, un, out);
}